// round 13
// baseline (speedup 1.0000x reference)
#include <cuda_runtime.h>
#include <math.h>

#define B_ 64
#define S_ 4096
#define H_ 512
#define A_ 256
#define IN_ 256
#define NCHUNK 64
#define CHUNK (S_ / NCHUNK)            // 64 rows per chunk
#define WARPS_B 8
#define ROWS_PER_WARP (CHUNK / WARPS_B) // 8

#define QT_TILES ((B_ / 16) * (H_ / 16))  // 4 x 32 = 128 GEMM tiles
#define TR_BLOCKS ((A_ / 32) * (H_ / 32)) // 128 blocks for Wv transpose

// Scratch (no allocations allowed) ------------------------------------------
__device__ float g_Q[B_ * A_];             // Q = x@Wq + bq
__device__ float g_qt[B_ * H_];            // folded query  q~ = Q @ Wk^T
__device__ float g_cst[B_];                // Q . bk
__device__ float g_pm[B_ * NCHUNK];        // per-chunk running max
__device__ float g_pl[B_ * NCHUNK];        // per-chunk exp-sum
__device__ float g_pc[B_ * NCHUNK * H_];   // per-chunk weighted hidden sum (8 MB)
__device__ float g_part[4 * B_ * H_];      // c-quarter partial contexts (normalized)
__device__ float g_WvT[A_ * H_];           // transposed Wv (A-major)

// ---------------------------------------------------------------------------
// Kernel A1: Q = x@Wq + bq  and  cst[b] = Q[b] . bk   (EXACT R9/R12 version)
__global__ __launch_bounds__(256) void q_kernel(
    const float* __restrict__ x, const float* __restrict__ Wq,
    const float* __restrict__ bq, const float* __restrict__ bk)
{
    const int b = blockIdx.x;
    const int a = threadIdx.x;
    __shared__ float shP[A_];

    const float* xr = x + b * IN_;
    float acc[8];
    #pragma unroll
    for (int k = 0; k < 8; ++k) acc[k] = 0.f;

    #pragma unroll 4
    for (int i = 0; i < IN_; i += 8) {
        #pragma unroll
        for (int k = 0; k < 8; ++k)
            acc[k] = fmaf(xr[i + k], Wq[(i + k) * A_ + a], acc[k]);
    }
    float q = 0.f;
    #pragma unroll
    for (int k = 0; k < 8; ++k) q += acc[k];
    q += bq[a];

    g_Q[b * A_ + a] = q;
    shP[a] = q * bk[a];
    __syncthreads();

    for (int s = 128; s > 0; s >>= 1) {
        if (a < s) shP[a] += shP[a + s];
        __syncthreads();
    }
    if (a == 0) g_cst[b] = shP[0];
}

// ---------------------------------------------------------------------------
// Kernel A2 (NEW): blocks [0, QT_TILES): TILED GEMM q~ = Q @ Wk^T.
//   16x16 output tile per block, K-slabs of 32 in shared. Global traffic
//   drops from 64 MB (warp-per-output) to ~4 MB (16x operand reuse).
// blocks [QT_TILES, QT_TILES+TR_BLOCKS): Wv transpose -> g_WvT.
__global__ __launch_bounds__(256) void prep_kernel(
    const float* __restrict__ Wk, const float* __restrict__ Wv)
{
    if (blockIdx.x < QT_TILES) {
        __shared__ float Qs[16][33];
        __shared__ float Ks[16][33];

        const int b0 = (blockIdx.x & 3) * 16;   // 4 tiles along B
        const int h0 = (blockIdx.x >> 2) * 16;  // 32 tiles along H
        const int tid = threadIdx.x;
        const int ty = tid >> 4;                // 0..15 (b within tile)
        const int tx = tid & 15;                // 0..15 (h within tile)
        const int lr = tid >> 5;                // 0..7  (load row)
        const int lc = tid & 31;                // 0..31 (load col)

        float acc = 0.f;
        #pragma unroll
        for (int kk = 0; kk < A_; kk += 32) {
            Qs[lr][lc]     = g_Q[(b0 + lr) * A_ + kk + lc];
            Qs[lr + 8][lc] = g_Q[(b0 + lr + 8) * A_ + kk + lc];
            Ks[lr][lc]     = Wk[(h0 + lr) * A_ + kk + lc];
            Ks[lr + 8][lc] = Wk[(h0 + lr + 8) * A_ + kk + lc];
            __syncthreads();
            #pragma unroll
            for (int c = 0; c < 32; ++c)
                acc = fmaf(Qs[ty][c], Ks[tx][c], acc);
            __syncthreads();
        }
        g_qt[(b0 + ty) * H_ + h0 + tx] = acc;
    } else {
        __shared__ float tile[32][33];
        const int bx = blockIdx.x - QT_TILES;  // 0..127
        const int a0 = (bx & 7) * 32;
        const int h0 = (bx >> 3) * 32;
        const int tx = threadIdx.x & 31;
        const int ty = threadIdx.x >> 5;       // 0..7

        #pragma unroll
        for (int i = 0; i < 4; ++i) {
            const int h = h0 + ty + i * 8;
            tile[ty + i * 8][tx] = Wv[h * A_ + a0 + tx];
        }
        __syncthreads();
        #pragma unroll
        for (int i = 0; i < 4; ++i) {
            const int a = a0 + ty + i * 8;
            g_WvT[a * H_ + h0 + tx] = tile[tx][ty + i * 8];
        }
    }
}

// ---------------------------------------------------------------------------
// Kernel B: streaming online-softmax pass over history_h. (EXACT R9 version:
// grid = (64,64) = 4096 CTAs, 8 warps x 8 rows, register q, pipelined loads.)
__global__ __launch_bounds__(256) void attn_pass_kernel(const float* __restrict__ hist)
{
    const int b     = blockIdx.y;
    const int chunk = blockIdx.x;
    const int tid   = threadIdx.x;
    const int w     = tid >> 5;
    const int lane  = tid & 31;

    float4 q4[4];
    const float4* qv = (const float4*)(g_qt + b * H_);
    #pragma unroll
    for (int j = 0; j < 4; ++j) q4[j] = qv[j * 32 + lane];

    const float cb = g_cst[b];
    const float inv_scale = 0.0625f; // 1/sqrt(256)

    float m = -INFINITY, l = 0.f;
    float4 acc[4];
    #pragma unroll
    for (int j = 0; j < 4; ++j) acc[j] = make_float4(0.f, 0.f, 0.f, 0.f);

    const int s0 = chunk * CHUNK + w * ROWS_PER_WARP;
    const float4* rowp = (const float4*)(hist + ((size_t)b * S_ + s0) * H_);
    const int row_stride4 = H_ / 4;

    float4 h4[4], n4[4];
    #pragma unroll
    for (int j = 0; j < 4; ++j) h4[j] = rowp[j * 32 + lane];

    #pragma unroll
    for (int r = 0; r < ROWS_PER_WARP; ++r) {
        if (r < ROWS_PER_WARP - 1) {
            const float4* np = rowp + (size_t)(r + 1) * row_stride4;
            #pragma unroll
            for (int j = 0; j < 4; ++j) n4[j] = np[j * 32 + lane];
        }

        float dot = 0.f;
        #pragma unroll
        for (int j = 0; j < 4; ++j) {
            dot = fmaf(h4[j].x, q4[j].x, dot);
            dot = fmaf(h4[j].y, q4[j].y, dot);
            dot = fmaf(h4[j].z, q4[j].z, dot);
            dot = fmaf(h4[j].w, q4[j].w, dot);
        }
        #pragma unroll
        for (int o = 16; o > 0; o >>= 1)
            dot += __shfl_xor_sync(0xffffffffu, dot, o);

        const float score = (dot + cb) * inv_scale;

        if (score > m) {                     // warp-uniform
            const float rsc = __expf(m - score);
            l *= rsc;
            #pragma unroll
            for (int j = 0; j < 4; ++j) {
                acc[j].x *= rsc; acc[j].y *= rsc; acc[j].z *= rsc; acc[j].w *= rsc;
            }
            m = score;
        }
        const float wgt = __expf(score - m);
        l += wgt;
        #pragma unroll
        for (int j = 0; j < 4; ++j) {
            acc[j].x = fmaf(wgt, h4[j].x, acc[j].x);
            acc[j].y = fmaf(wgt, h4[j].y, acc[j].y);
            acc[j].z = fmaf(wgt, h4[j].z, acc[j].z);
            acc[j].w = fmaf(wgt, h4[j].w, acc[j].w);
        }

        #pragma unroll
        for (int j = 0; j < 4; ++j) h4[j] = n4[j];
    }

    // ---- deterministic block combine ----
    __shared__ float s_m[WARPS_B], s_l[WARPS_B], s_scale[WARPS_B];
    __shared__ float s_c[WARPS_B][H_];   // 16 KB
    if (lane == 0) { s_m[w] = m; s_l[w] = l; }
    __syncthreads();
    if (tid == 0) {
        float mb = s_m[0];
        #pragma unroll
        for (int i = 1; i < WARPS_B; ++i) mb = fmaxf(mb, s_m[i]);
        float lb = 0.f;
        #pragma unroll
        for (int i = 0; i < WARPS_B; ++i) {
            const float sc_ = __expf(s_m[i] - mb);
            s_scale[i] = sc_;
            lb = fmaf(sc_, s_l[i], lb);
        }
        const int idx = b * NCHUNK + chunk;
        g_pm[idx] = mb;
        g_pl[idx] = lb;
    }
    __syncthreads();

    const float sc_w = s_scale[w];
    #pragma unroll
    for (int j = 0; j < 4; ++j) {
        float4 v = acc[j];
        v.x *= sc_w; v.y *= sc_w; v.z *= sc_w; v.w *= sc_w;
        ((float4*)&s_c[w][j * 128])[lane] = v;
    }
    __syncthreads();

    float* gout = g_pc + (size_t)(b * NCHUNK + chunk) * H_;
    for (int hh = tid; hh < H_; hh += 256) {
        float t = 0.f;
        #pragma unroll
        for (int wi = 0; wi < WARPS_B; ++wi) t += s_c[wi][hh];
        gout[hh] = t;
    }
}

// ---------------------------------------------------------------------------
// Kernel C1: partial combine over a 16-chunk quarter, normalized.
// grid = 512 blocks, block = 256. (R10-R12 measured ~6.5us.)
__global__ __launch_bounds__(256) void combine_part_kernel()
{
    const int idx = blockIdx.x;
    const int b  = idx >> 3;
    const int hs = (idx >> 2) & 1;
    const int cq = idx & 3;
    const int h  = hs * 256 + threadIdx.x;

    __shared__ float s_scale[16];

    if (threadIdx.x < 32) {
        const int lane = threadIdx.x;
        const float m0 = g_pm[b * NCHUNK + lane];
        const float m1 = g_pm[b * NCHUNK + lane + 32];
        const float l0 = g_pl[b * NCHUNK + lane];
        const float l1 = g_pl[b * NCHUNK + lane + 32];
        float mm = fmaxf(m0, m1);
        #pragma unroll
        for (int o = 16; o > 0; o >>= 1)
            mm = fmaxf(mm, __shfl_xor_sync(0xffffffffu, mm, o));
        float ls = fmaf(__expf(m0 - mm), l0, __expf(m1 - mm) * l1);
        #pragma unroll
        for (int o = 16; o > 0; o >>= 1)
            ls += __shfl_xor_sync(0xffffffffu, ls, o);
        const float invl = 1.0f / ls;
        if (lane < 16) {
            const int c = cq * 16 + lane;
            s_scale[lane] = __expf(g_pm[b * NCHUNK + c] - mm) * invl;
        }
    }
    __syncthreads();

    const float* base = g_pc + ((size_t)b * NCHUNK + cq * 16) * H_ + h;
    float t = 0.f;
    #pragma unroll
    for (int c = 0; c < 16; ++c)
        t = fmaf(s_scale[c], base[(size_t)c * H_], t);
    g_part[(size_t)cq * (B_ * H_) + b * H_ + h] = t;
}

// ---------------------------------------------------------------------------
// Kernel C2 (fused add + GEMV): out[b,a] = (sum of 4 quarter partials) . WvT[a]
// + bv[a] — one WARP per output. grid = 2048, block = 256. L2-hot reads.
__global__ __launch_bounds__(256) void out_kernel(
    const float* __restrict__ bv, float* __restrict__ out)
{
    const int gw   = blockIdx.x * WARPS_B + (threadIdx.x >> 5);
    const int lane = threadIdx.x & 31;
    const int b = gw >> 8;          // /256
    const int a = gw & (A_ - 1);    // %256

    const float* p0 = g_part + b * H_;
    const float* p1 = p0 + (size_t)(B_ * H_);
    const float* p2 = p0 + 2 * (size_t)(B_ * H_);
    const float* p3 = p0 + 3 * (size_t)(B_ * H_);
    const float* wr = g_WvT + a * H_;

    float acc = 0.f;
    #pragma unroll
    for (int j = 0; j < H_ / 32; ++j) {
        const int h = j * 32 + lane;
        const float ctxh = (p0[h] + p1[h]) + (p2[h] + p3[h]);
        acc = fmaf(ctxh, wr[h], acc);
    }
    #pragma unroll
    for (int o = 16; o > 0; o >>= 1)
        acc += __shfl_xor_sync(0xffffffffu, acc, o);
    if (lane == 0) out[b * A_ + a] = acc + bv[a];
}

// ---------------------------------------------------------------------------
extern "C" void kernel_launch(void* const* d_in, const int* in_sizes, int n_in,
                              void* d_out, int out_size)
{
    const float* x    = (const float*)d_in[0];
    const float* hist = (const float*)d_in[1];
    const float* Wq   = (const float*)d_in[2];
    const float* bq   = (const float*)d_in[3];
    const float* Wk   = (const float*)d_in[4];
    const float* bk   = (const float*)d_in[5];
    const float* Wv   = (const float*)d_in[6];
    const float* bv   = (const float*)d_in[7];
    float* out = (float*)d_out;

    q_kernel<<<B_, 256>>>(x, Wq, bq, bk);
    prep_kernel<<<QT_TILES + TR_BLOCKS, 256>>>(Wk, Wv);
    attn_pass_kernel<<<dim3(NCHUNK, B_), 256>>>(hist);
    combine_part_kernel<<<B_ * 8, 256>>>();
    out_kernel<<<(B_ * A_) / WARPS_B, 256>>>(bv, out);
}

// round 14
// speedup vs baseline: 1.1225x; 1.1225x over previous
#include <cuda_runtime.h>
#include <math.h>

#define B_ 64
#define S_ 4096
#define H_ 512
#define A_ 256
#define IN_ 256
#define NCHUNK 64
#define CHUNK (S_ / NCHUNK)            // 64 rows per chunk
#define WARPS_B 8
#define ROWS_PER_WARP (CHUNK / WARPS_B) // 8

#define QT_TILES ((B_ / 16) * (H_ / 16))  // 4 x 32 = 128 GEMM tiles
#define TR_BLOCKS ((A_ / 32) * (H_ / 32)) // 128 blocks for Wv transpose
#define CST_BLOCKS (B_ / WARPS_B)         // 8 blocks, warp-per-batch

// Scratch (no allocations allowed) ------------------------------------------
__device__ float g_Qp[4 * B_ * A_];        // Q partials (i-quarters; q0 holds +bq)
__device__ float g_qt[B_ * H_];            // folded query  q~ = Q @ Wk^T
__device__ float g_cst[B_];                // Q . bk
__device__ float g_pm[B_ * NCHUNK];        // per-chunk running max
__device__ float g_pl[B_ * NCHUNK];        // per-chunk exp-sum
__device__ float g_pc[B_ * NCHUNK * H_];   // per-chunk weighted hidden sum (8 MB)
__device__ float g_part[4 * B_ * H_];      // c-quarter partial contexts (normalized)
__device__ float g_WvT[A_ * H_];           // transposed Wv (A-major)

// ---------------------------------------------------------------------------
// Kernel A1: Q partials. grid = (4, 64): blockIdx.x = i-quarter, .y = batch.
// Each block reduces 64 input dims (8 rounds of 8 chains) — 4x the previous
// parallelism, 1/4 the serial latency chain. Quarter 0 folds in bq.
__global__ __launch_bounds__(256) void q_kernel(
    const float* __restrict__ x, const float* __restrict__ Wq,
    const float* __restrict__ bq)
{
    const int ip = blockIdx.x;            // 0..3
    const int b  = blockIdx.y;
    const int a  = threadIdx.x;

    const float* xr = x + b * IN_ + ip * 64;
    const float* wq = Wq + (size_t)(ip * 64) * A_ + a;

    float acc[8];
    #pragma unroll
    for (int k = 0; k < 8; ++k) acc[k] = 0.f;

    #pragma unroll
    for (int i = 0; i < 64; i += 8) {
        #pragma unroll
        for (int k = 0; k < 8; ++k)
            acc[k] = fmaf(xr[i + k], wq[(size_t)(i + k) * A_], acc[k]);
    }
    float q = ((acc[0] + acc[1]) + (acc[2] + acc[3]))
            + ((acc[4] + acc[5]) + (acc[6] + acc[7]));
    if (ip == 0) q += bq[a];
    g_Qp[(ip * B_ + b) * A_ + a] = q;
}

// ---------------------------------------------------------------------------
// Kernel A2 (fused): blocks [0, QT_TILES): tiled GEMM q~ = Q @ Wk^T
//   (Q assembled from the 4 partials while staging into smem);
// blocks [QT_TILES, +TR_BLOCKS): Wv transpose;
// blocks [QT_TILES+TR_BLOCKS, +CST_BLOCKS): cst[b] = Q[b].bk, warp-per-batch.
__global__ __launch_bounds__(256) void prep_kernel(
    const float* __restrict__ Wk, const float* __restrict__ Wv,
    const float* __restrict__ bk)
{
    if (blockIdx.x < QT_TILES) {
        __shared__ float Qs[16][33];
        __shared__ float Ks[16][33];

        const int b0 = (blockIdx.x & 3) * 16;   // 4 tiles along B
        const int h0 = (blockIdx.x >> 2) * 16;  // 32 tiles along H
        const int tid = threadIdx.x;
        const int ty = tid >> 4;                // 0..15 (b within tile)
        const int tx = tid & 15;                // 0..15 (h within tile)
        const int lr = tid >> 5;                // 0..7  (load row)
        const int lc = tid & 31;                // 0..31 (load col)

        float acc = 0.f;
        #pragma unroll
        for (int kk = 0; kk < A_; kk += 32) {
            #pragma unroll
            for (int rr = 0; rr < 2; ++rr) {
                const int row = b0 + lr + rr * 8;
                const int col = kk + lc;
                float qv = g_Qp[(0 * B_ + row) * A_ + col]
                         + g_Qp[(1 * B_ + row) * A_ + col]
                         + g_Qp[(2 * B_ + row) * A_ + col]
                         + g_Qp[(3 * B_ + row) * A_ + col];
                Qs[lr + rr * 8][lc] = qv;
                Ks[lr + rr * 8][lc] = Wk[(h0 + lr + rr * 8) * A_ + col];
            }
            __syncthreads();
            #pragma unroll
            for (int c = 0; c < 32; ++c)
                acc = fmaf(Qs[ty][c], Ks[tx][c], acc);
            __syncthreads();
        }
        g_qt[(b0 + ty) * H_ + h0 + tx] = acc;
    } else if (blockIdx.x < QT_TILES + TR_BLOCKS) {
        __shared__ float tile[32][33];
        const int bx = blockIdx.x - QT_TILES;  // 0..127
        const int a0 = (bx & 7) * 32;
        const int h0 = (bx >> 3) * 32;
        const int tx = threadIdx.x & 31;
        const int ty = threadIdx.x >> 5;       // 0..7

        #pragma unroll
        for (int i = 0; i < 4; ++i) {
            const int h = h0 + ty + i * 8;
            tile[ty + i * 8][tx] = Wv[h * A_ + a0 + tx];
        }
        __syncthreads();
        #pragma unroll
        for (int i = 0; i < 4; ++i) {
            const int a = a0 + ty + i * 8;
            g_WvT[a * H_ + h0 + tx] = tile[tx][ty + i * 8];
        }
    } else {
        // ---- cst: warp-per-batch ----
        const int bb = blockIdx.x - QT_TILES - TR_BLOCKS;  // 0..7
        const int w = threadIdx.x >> 5;
        const int lane = threadIdx.x & 31;
        const int b = bb * WARPS_B + w;

        float acc = 0.f;
        #pragma unroll
        for (int j = 0; j < A_ / 32; ++j) {
            const int a = j * 32 + lane;
            const float qv = g_Qp[(0 * B_ + b) * A_ + a]
                           + g_Qp[(1 * B_ + b) * A_ + a]
                           + g_Qp[(2 * B_ + b) * A_ + a]
                           + g_Qp[(3 * B_ + b) * A_ + a];
            acc = fmaf(qv, bk[a], acc);
        }
        #pragma unroll
        for (int o = 16; o > 0; o >>= 1)
            acc += __shfl_xor_sync(0xffffffffu, acc, o);
        if (lane == 0) g_cst[b] = acc;
    }
}

// ---------------------------------------------------------------------------
// Kernel B: streaming online-softmax pass over history_h. (EXACT R9 version:
// grid = (64,64) = 4096 CTAs, 8 warps x 8 rows, register q, pipelined loads.)
__global__ __launch_bounds__(256) void attn_pass_kernel(const float* __restrict__ hist)
{
    const int b     = blockIdx.y;
    const int chunk = blockIdx.x;
    const int tid   = threadIdx.x;
    const int w     = tid >> 5;
    const int lane  = tid & 31;

    float4 q4[4];
    const float4* qv = (const float4*)(g_qt + b * H_);
    #pragma unroll
    for (int j = 0; j < 4; ++j) q4[j] = qv[j * 32 + lane];

    const float cb = g_cst[b];
    const float inv_scale = 0.0625f; // 1/sqrt(256)

    float m = -INFINITY, l = 0.f;
    float4 acc[4];
    #pragma unroll
    for (int j = 0; j < 4; ++j) acc[j] = make_float4(0.f, 0.f, 0.f, 0.f);

    const int s0 = chunk * CHUNK + w * ROWS_PER_WARP;
    const float4* rowp = (const float4*)(hist + ((size_t)b * S_ + s0) * H_);
    const int row_stride4 = H_ / 4;

    float4 h4[4], n4[4];
    #pragma unroll
    for (int j = 0; j < 4; ++j) h4[j] = rowp[j * 32 + lane];

    #pragma unroll
    for (int r = 0; r < ROWS_PER_WARP; ++r) {
        if (r < ROWS_PER_WARP - 1) {
            const float4* np = rowp + (size_t)(r + 1) * row_stride4;
            #pragma unroll
            for (int j = 0; j < 4; ++j) n4[j] = np[j * 32 + lane];
        }

        float dot = 0.f;
        #pragma unroll
        for (int j = 0; j < 4; ++j) {
            dot = fmaf(h4[j].x, q4[j].x, dot);
            dot = fmaf(h4[j].y, q4[j].y, dot);
            dot = fmaf(h4[j].z, q4[j].z, dot);
            dot = fmaf(h4[j].w, q4[j].w, dot);
        }
        #pragma unroll
        for (int o = 16; o > 0; o >>= 1)
            dot += __shfl_xor_sync(0xffffffffu, dot, o);

        const float score = (dot + cb) * inv_scale;

        if (score > m) {                     // warp-uniform
            const float rsc = __expf(m - score);
            l *= rsc;
            #pragma unroll
            for (int j = 0; j < 4; ++j) {
                acc[j].x *= rsc; acc[j].y *= rsc; acc[j].z *= rsc; acc[j].w *= rsc;
            }
            m = score;
        }
        const float wgt = __expf(score - m);
        l += wgt;
        #pragma unroll
        for (int j = 0; j < 4; ++j) {
            acc[j].x = fmaf(wgt, h4[j].x, acc[j].x);
            acc[j].y = fmaf(wgt, h4[j].y, acc[j].y);
            acc[j].z = fmaf(wgt, h4[j].z, acc[j].z);
            acc[j].w = fmaf(wgt, h4[j].w, acc[j].w);
        }

        #pragma unroll
        for (int j = 0; j < 4; ++j) h4[j] = n4[j];
    }

    // ---- deterministic block combine ----
    __shared__ float s_m[WARPS_B], s_l[WARPS_B], s_scale[WARPS_B];
    __shared__ float s_c[WARPS_B][H_];   // 16 KB
    if (lane == 0) { s_m[w] = m; s_l[w] = l; }
    __syncthreads();
    if (tid == 0) {
        float mb = s_m[0];
        #pragma unroll
        for (int i = 1; i < WARPS_B; ++i) mb = fmaxf(mb, s_m[i]);
        float lb = 0.f;
        #pragma unroll
        for (int i = 0; i < WARPS_B; ++i) {
            const float sc_ = __expf(s_m[i] - mb);
            s_scale[i] = sc_;
            lb = fmaf(sc_, s_l[i], lb);
        }
        const int idx = b * NCHUNK + chunk;
        g_pm[idx] = mb;
        g_pl[idx] = lb;
    }
    __syncthreads();

    const float sc_w = s_scale[w];
    #pragma unroll
    for (int j = 0; j < 4; ++j) {
        float4 v = acc[j];
        v.x *= sc_w; v.y *= sc_w; v.z *= sc_w; v.w *= sc_w;
        ((float4*)&s_c[w][j * 128])[lane] = v;
    }
    __syncthreads();

    float* gout = g_pc + (size_t)(b * NCHUNK + chunk) * H_;
    for (int hh = tid; hh < H_; hh += 256) {
        float t = 0.f;
        #pragma unroll
        for (int wi = 0; wi < WARPS_B; ++wi) t += s_c[wi][hh];
        gout[hh] = t;
    }
}

// ---------------------------------------------------------------------------
// Kernel C1: partial combine over a 16-chunk quarter, normalized.
// grid = 512 blocks, block = 256. (R10-R13 measured ~6.5us.)
__global__ __launch_bounds__(256) void combine_part_kernel()
{
    const int idx = blockIdx.x;
    const int b  = idx >> 3;
    const int hs = (idx >> 2) & 1;
    const int cq = idx & 3;
    const int h  = hs * 256 + threadIdx.x;

    __shared__ float s_scale[16];

    if (threadIdx.x < 32) {
        const int lane = threadIdx.x;
        const float m0 = g_pm[b * NCHUNK + lane];
        const float m1 = g_pm[b * NCHUNK + lane + 32];
        const float l0 = g_pl[b * NCHUNK + lane];
        const float l1 = g_pl[b * NCHUNK + lane + 32];
        float mm = fmaxf(m0, m1);
        #pragma unroll
        for (int o = 16; o > 0; o >>= 1)
            mm = fmaxf(mm, __shfl_xor_sync(0xffffffffu, mm, o));
        float ls = fmaf(__expf(m0 - mm), l0, __expf(m1 - mm) * l1);
        #pragma unroll
        for (int o = 16; o > 0; o >>= 1)
            ls += __shfl_xor_sync(0xffffffffu, ls, o);
        const float invl = 1.0f / ls;
        if (lane < 16) {
            const int c = cq * 16 + lane;
            s_scale[lane] = __expf(g_pm[b * NCHUNK + c] - mm) * invl;
        }
    }
    __syncthreads();

    const float* base = g_pc + ((size_t)b * NCHUNK + cq * 16) * H_ + h;
    float t = 0.f;
    #pragma unroll
    for (int c = 0; c < 16; ++c)
        t = fmaf(s_scale[c], base[(size_t)c * H_], t);
    g_part[(size_t)cq * (B_ * H_) + b * H_ + h] = t;
}

// ---------------------------------------------------------------------------
// Kernel C2 (fused add + GEMV): out[b,a] = (sum of 4 quarter partials) . WvT[a]
// + bv[a] — one WARP per output. grid = 2048, block = 256. L2-hot reads.
__global__ __launch_bounds__(256) void out_kernel(
    const float* __restrict__ bv, float* __restrict__ out)
{
    const int gw   = blockIdx.x * WARPS_B + (threadIdx.x >> 5);
    const int lane = threadIdx.x & 31;
    const int b = gw >> 8;          // /256
    const int a = gw & (A_ - 1);    // %256

    const float* p0 = g_part + b * H_;
    const float* p1 = p0 + (size_t)(B_ * H_);
    const float* p2 = p0 + 2 * (size_t)(B_ * H_);
    const float* p3 = p0 + 3 * (size_t)(B_ * H_);
    const float* wr = g_WvT + a * H_;

    float acc = 0.f;
    #pragma unroll
    for (int j = 0; j < H_ / 32; ++j) {
        const int h = j * 32 + lane;
        const float ctxh = (p0[h] + p1[h]) + (p2[h] + p3[h]);
        acc = fmaf(ctxh, wr[h], acc);
    }
    #pragma unroll
    for (int o = 16; o > 0; o >>= 1)
        acc += __shfl_xor_sync(0xffffffffu, acc, o);
    if (lane == 0) out[b * A_ + a] = acc + bv[a];
}

// ---------------------------------------------------------------------------
extern "C" void kernel_launch(void* const* d_in, const int* in_sizes, int n_in,
                              void* d_out, int out_size)
{
    const float* x    = (const float*)d_in[0];
    const float* hist = (const float*)d_in[1];
    const float* Wq   = (const float*)d_in[2];
    const float* bq   = (const float*)d_in[3];
    const float* Wk   = (const float*)d_in[4];
    const float* bk   = (const float*)d_in[5];
    const float* Wv   = (const float*)d_in[6];
    const float* bv   = (const float*)d_in[7];
    float* out = (float*)d_out;

    q_kernel<<<dim3(4, B_), 256>>>(x, Wq, bq);
    prep_kernel<<<QT_TILES + TR_BLOCKS + CST_BLOCKS, 256>>>(Wk, Wv, bk);
    attn_pass_kernel<<<dim3(NCHUNK, B_), 256>>>(hist);
    combine_part_kernel<<<B_ * 8, 256>>>();
    out_kernel<<<(B_ * A_) / WARPS_B, 256>>>(bv, out);
}